// round 4
// baseline (speedup 1.0000x reference)
#include <cuda_runtime.h>
#include <math.h>
#include <stdint.h>

#define VGRID   100
#define NBATCH  8
#define NPTS    65536
#define NPOINTS (NBATCH * NPTS)                   // 524288
#define NVOX    (NBATCH * VGRID * VGRID * VGRID)  // 8,000,000
#define COUT    10
#define NWORDS  (NVOX / 32)                       // 250,000
#define NF4     (NVOX * COUT / 4)                 // 20,000,000 output float4s

// 32B record per voxel: lo=[x,y,z,f0], hi=[f1,f2,cnt,pad]. Indexed g_acc[2v], g_acc[2v+1].
// Zero at module load; clean_kernel keeps it zero across graph replays.
__device__ __align__(32) float4 g_acc[(size_t)NVOX * 2];
__device__ uint32_t g_bits[NWORDS];

// ---------------------------------------------------------------------------
// Clean: runs FIRST. Zeros records/bitmap touched by the previous replay.
// Each warp owns exactly one bitmap word (256-thread blocks, aligned), so the
// word test is warp-uniform and empty words cost one broadcast load.
// ---------------------------------------------------------------------------
__global__ void clean_kernel() {
    int v = blockIdx.x * 256 + threadIdx.x;
    uint32_t word = g_bits[v >> 5];
    if (word == 0u) return;                      // warp-uniform skip
    if ((word >> (v & 31)) & 1u) {
        float4 z = make_float4(0.f, 0.f, 0.f, 0.f);
        g_acc[2 * (size_t)v]     = z;
        g_acc[2 * (size_t)v + 1] = z;
    }
    if ((v & 31) == 0) g_bits[v >> 5] = 0u;
}

// ---------------------------------------------------------------------------
// Scatter: 4 points per thread, 6x LDG.128 input loads, 3 atomics per point.
// Binning (verified rounds 1-2): idx = floor((c+RES)/RES), keep [1,100].
// ---------------------------------------------------------------------------
__global__ void scatter_kernel(const float4* __restrict__ coords4,
                               const float4* __restrict__ feats4) {
    int t = blockIdx.x * blockDim.x + threadIdx.x;   // < NPOINTS/4
    const float RES = 1.0f / 100.0f;

    float4 c0 = coords4[3 * t], c1 = coords4[3 * t + 1], c2 = coords4[3 * t + 2];
    float4 g0 = feats4 [3 * t], g1 = feats4 [3 * t + 1], g2 = feats4 [3 * t + 2];

    float cx[4] = {c0.x, c0.w, c1.z, c2.y};
    float cy[4] = {c0.y, c1.x, c1.w, c2.z};
    float cz[4] = {c0.z, c1.y, c2.x, c2.w};
    float fa[4] = {g0.x, g0.w, g1.z, g2.y};
    float fb[4] = {g0.y, g1.x, g1.w, g2.z};
    float fc[4] = {g0.z, g1.y, g2.x, g2.w};

    int b = t >> 14;   // (4t)/65536: 4 points never straddle a batch

    #pragma unroll
    for (int j = 0; j < 4; j++) {
        float x = cx[j], y = cy[j], z = cz[j];
        int ix = (int)floorf((x + RES) / RES);
        int iy = (int)floorf((y + RES) / RES);
        int iz = (int)floorf((z + RES) / RES);
        if (ix < 1 || ix > VGRID || iy < 1 || iy > VGRID || iz < 1 || iz > VGRID)
            continue;
        int v = (((b * VGRID + (ix - 1)) * VGRID + (iy - 1)) * VGRID + (iz - 1));
        float4* rec = g_acc + (size_t)v * 2;
        asm volatile("red.global.add.v4.f32 [%0], {%1, %2, %3, %4};"
                     :: "l"(rec), "f"(x), "f"(y), "f"(z), "f"(fa[j]) : "memory");
        asm volatile("red.global.add.v4.f32 [%0], {%1, %2, %3, %4};"
                     :: "l"(rec + 1), "f"(fb[j]), "f"(fc[j]), "f"(1.0f), "f"(0.0f)
                     : "memory");
        atomicOr(&g_bits[v >> 5], 1u << (v & 31));
    }
}

// ---------------------------------------------------------------------------
// Finalize: one thread per OUTPUT float4 (perfectly coalesced STG.128).
// lcm(4,10)=20 floats => 5 float4 patterns per voxel pair (va=2q, vb=2q+1):
//   p0: a.c0-3   p1: a.c4,c5,i/100,j/100   p2: k/100,occ_a,b.c0,b.c1
//   p3: b.c2-5   p4: i/100,j/100,k/100,occ_b
// Records are READ-ONLY here (clean_kernel owns zeroing) -> no races.
// ---------------------------------------------------------------------------
__global__ void finalize_kernel(float4* __restrict__ out) {
    int idx = blockIdx.x * 256 + threadIdx.x;    // < NF4
    int q = idx / 5;
    int p = idx - q * 5;
    int va = q * 2;

    uint32_t word = g_bits[va >> 5];             // va,vb share this word
    int sh = va & 31;

    float4 r;
    if (p == 0) {
        r = make_float4(0.f, 0.f, 0.f, 0.f);
        if ((word >> sh) & 1u) {
            float4 lo = g_acc[2 * (size_t)va];
            float4 hi = g_acc[2 * (size_t)va + 1];
            float inv = 1.0f / hi.z;             // occupied => cnt >= 1
            r = make_float4(lo.x * inv, lo.y * inv, lo.z * inv, lo.w * inv);
        }
    } else if (p == 1) {
        float m4 = 0.f, m5 = 0.f;
        if ((word >> sh) & 1u) {
            float4 hi = g_acc[2 * (size_t)va + 1];
            float inv = 1.0f / hi.z;
            m4 = hi.x * inv; m5 = hi.y * inv;
        }
        int tt = va / VGRID;
        int j = tt % VGRID;
        int i = (tt / VGRID) % VGRID;
        r = make_float4(m4, m5, (float)i * 0.01f, (float)j * 0.01f);
    } else if (p == 2) {
        int vb = va + 1;
        float occa = (float)((word >> sh) & 1u);
        float mx = 0.f, my = 0.f;
        if ((word >> (sh + 1)) & 1u) {
            float4 lo = g_acc[2 * (size_t)vb];
            float4 hi = g_acc[2 * (size_t)vb + 1];
            float inv = 1.0f / hi.z;
            mx = lo.x * inv; my = lo.y * inv;
        }
        int k = va % VGRID;
        r = make_float4((float)k * 0.01f, occa, mx, my);
    } else if (p == 3) {
        int vb = va + 1;
        r = make_float4(0.f, 0.f, 0.f, 0.f);
        if ((word >> (sh + 1)) & 1u) {
            float4 lo = g_acc[2 * (size_t)vb];
            float4 hi = g_acc[2 * (size_t)vb + 1];
            float inv = 1.0f / hi.z;
            r = make_float4(lo.z * inv, lo.w * inv, hi.x * inv, hi.y * inv);
        }
    } else {
        int vb = va + 1;
        float occb = (float)((word >> (sh + 1)) & 1u);
        int k = vb % VGRID;
        int tt = vb / VGRID;
        int j = tt % VGRID;
        int i = (tt / VGRID) % VGRID;
        r = make_float4((float)i * 0.01f, (float)j * 0.01f, (float)k * 0.01f, occb);
    }
    out[idx] = r;
}

// ---------------------------------------------------------------------------
extern "C" void kernel_launch(void* const* d_in, const int* in_sizes, int n_in,
                              void* d_out, int out_size) {
    const float4* coords4 = (const float4*)d_in[0];
    const float4* feats4  = (const float4*)d_in[1];
    float4* out = (float4*)d_out;

    clean_kernel   <<<NVOX / 256, 256>>>();
    scatter_kernel <<<NPOINTS / 4 / 256, 256>>>(coords4, feats4);
    finalize_kernel<<<NF4 / 256, 256>>>(out);
}

// round 5
// speedup vs baseline: 1.3894x; 1.3894x over previous
#include <cuda_runtime.h>
#include <math.h>
#include <stdint.h>

#define VGRID   100
#define NBATCH  8
#define NPTS    65536
#define NPOINTS (NBATCH * NPTS)                   // 524288
#define NVOX    (NBATCH * VGRID * VGRID * VGRID)  // 8,000,000
#define COUT    10
#define NWORDS  (NVOX / 32)                       // 250,000

// 32B record per voxel: lo=[x,y,z,f0], hi=[f1,f2,cnt,pad].
// Zero at module load; finalize self-cleans (same thread reads then zeroes its
// own record => race-free, graph-replay safe; proven in round 2).
__device__ __align__(32) float4 g_acc[(size_t)NVOX * 2];
__device__ uint32_t g_bits[NWORDS];

// ---------------------------------------------------------------------------
// Scatter: 4 points per thread, 6x LDG.128 input loads, 3 atomics per point.
// Binning (verified rounds 1-4): idx = floor((c+RES)/RES), keep [1,100].
// ---------------------------------------------------------------------------
__global__ void scatter_kernel(const float4* __restrict__ coords4,
                               const float4* __restrict__ feats4) {
    int t = blockIdx.x * blockDim.x + threadIdx.x;   // < NPOINTS/4
    const float RES = 1.0f / 100.0f;

    float4 c0 = coords4[3 * t], c1 = coords4[3 * t + 1], c2 = coords4[3 * t + 2];
    float4 g0 = feats4 [3 * t], g1 = feats4 [3 * t + 1], g2 = feats4 [3 * t + 2];

    float cx[4] = {c0.x, c0.w, c1.z, c2.y};
    float cy[4] = {c0.y, c1.x, c1.w, c2.z};
    float cz[4] = {c0.z, c1.y, c2.x, c2.w};
    float fa[4] = {g0.x, g0.w, g1.z, g2.y};
    float fb[4] = {g0.y, g1.x, g1.w, g2.z};
    float fc[4] = {g0.z, g1.y, g2.x, g2.w};

    int b = t >> 14;   // (4t)/65536: 4 points never straddle a batch

    #pragma unroll
    for (int j = 0; j < 4; j++) {
        float x = cx[j], y = cy[j], z = cz[j];
        int ix = (int)floorf((x + RES) / RES);
        int iy = (int)floorf((y + RES) / RES);
        int iz = (int)floorf((z + RES) / RES);
        if (ix < 1 || ix > VGRID || iy < 1 || iy > VGRID || iz < 1 || iz > VGRID)
            continue;
        int v = (((b * VGRID + (ix - 1)) * VGRID + (iy - 1)) * VGRID + (iz - 1));
        float4* rec = g_acc + (size_t)v * 2;
        asm volatile("red.global.add.v4.f32 [%0], {%1, %2, %3, %4};"
                     :: "l"(rec), "f"(x), "f"(y), "f"(z), "f"(fa[j]) : "memory");
        asm volatile("red.global.add.v4.f32 [%0], {%1, %2, %3, %4};"
                     :: "l"(rec + 1), "f"(fb[j]), "f"(fc[j]), "f"(1.0f), "f"(0.0f)
                     : "memory");
        atomicOr(&g_bits[v >> 5], 1u << (v & 31));
    }
}

// ---------------------------------------------------------------------------
// Finalize: 256 threads handle 512 voxels (2 per thread), stage 5120 floats
// in smem, then 1280 coalesced STG.128 streaming stores per block.
// Integrated self-clean: the thread that reads a record zeroes it; lane with
// (v&31)==0 clears its bitmap word. Grid = NVOX/512 = 15625 (exact).
// ---------------------------------------------------------------------------
__global__ void finalize_kernel(float4* __restrict__ out) {
    __shared__ float sh[512 * COUT];

    int base = blockIdx.x * 512;

    #pragma unroll
    for (int h = 0; h < 2; h++) {
        int v = base + h * 256 + threadIdx.x;

        uint32_t word = g_bits[v >> 5];
        bool occ = (word >> (v & 31)) & 1u;

        float m0 = 0.f, m1 = 0.f, m2 = 0.f, m3 = 0.f, m4 = 0.f, m5 = 0.f;
        if (occ) {
            float4 lo = __ldcs(&g_acc[2 * (size_t)v]);
            float4 hi = __ldcs(&g_acc[2 * (size_t)v + 1]);
            float inv = 1.0f / hi.z;             // occupied => cnt >= 1
            m0 = lo.x * inv; m1 = lo.y * inv; m2 = lo.z * inv;
            m3 = lo.w * inv; m4 = hi.x * inv; m5 = hi.y * inv;
            float4 z = make_float4(0.f, 0.f, 0.f, 0.f);
            g_acc[2 * (size_t)v]     = z;        // self-clean for next replay
            g_acc[2 * (size_t)v + 1] = z;
        }
        if ((v & 31) == 0 && word != 0u)
            g_bits[v >> 5] = 0u;

        // v = ((b*100 + i)*100 + j)*100 + k
        int k = v % VGRID;
        int t = v / VGRID;
        int j = t % VGRID;
        int i = (t / VGRID) % VGRID;

        float* r = sh + (h * 256 + threadIdx.x) * COUT;
        r[0] = m0; r[1] = m1; r[2] = m2; r[3] = m3; r[4] = m4; r[5] = m5;
        r[6] = (float)i * 0.01f;
        r[7] = (float)j * 0.01f;
        r[8] = (float)k * 0.01f;
        r[9] = occ ? 1.0f : 0.0f;
    }

    __syncthreads();

    // 5120 floats = 1280 float4 per block; 5 exact iterations of 256 lanes.
    float4* dst = out + (size_t)blockIdx.x * 1280;
    const float4* src = reinterpret_cast<const float4*>(sh);
    #pragma unroll
    for (int q = 0; q < 1280; q += 256)
        __stcs(dst + q + threadIdx.x, src[q + threadIdx.x]);
}

// ---------------------------------------------------------------------------
extern "C" void kernel_launch(void* const* d_in, const int* in_sizes, int n_in,
                              void* d_out, int out_size) {
    const float4* coords4 = (const float4*)d_in[0];
    const float4* feats4  = (const float4*)d_in[1];
    float4* out = (float4*)d_out;

    scatter_kernel <<<NPOINTS / 4 / 256, 256>>>(coords4, feats4);
    finalize_kernel<<<NVOX / 512, 256>>>(out);
}